// round 10
// baseline (speedup 1.0000x reference)
#include <cuda_runtime.h>

// FiniteDifference: x [B=4, T=16, H=128, W=128, C=16] fp32
// out = concat(dy (d/dH), dx (d/dW), dz (d/dT)); central diff, zero pad.
//
// R10: persistent grid-stride variant of the established roofline kernel.
// Model (verified R1-R9): ~201 MB compulsory writes drain at ~5.3 TB/s
// (path/pattern-independent); input is L2-resident. Remaining slack is
// wave-structure overhead: 16384 CTAs = ~14 waves x ~2360 cyc transitions.
// One wave of 1184 CTAs (148 SMs x 8) with a grid-stride loop removes
// wave transitions and lets the compiler pipeline next-iter loads under
// pending stores.

#define N4_TOTAL (4 * 16 * 128 * 128 * 4)  // 4,194,304 float4 elems per output
#define NBLOCKS  1184                       // 148 SMs x 8 CTAs (256 thr, 30 regs)

__device__ __forceinline__ float4 sub4(float4 a, float4 b) {
    return make_float4(a.x - b.x, a.y - b.y, a.z - b.z, a.w - b.w);
}

__global__ void __launch_bounds__(256)
fd_kernel(const float4* __restrict__ x, float4* __restrict__ out)
{
    const float4 zero = make_float4(0.f, 0.f, 0.f, 0.f);
    const int stride = NBLOCKS * 256;

    for (int i = blockIdx.x * 256 + threadIdx.x; i < N4_TOTAL; i += stride) {
        int w = (i >> 2)  & 127;
        int h = (i >> 9)  & 127;
        int t = (i >> 16) & 15;

        float4 hp = (h < 127) ? x[i + 512]   : zero;
        float4 hm = (h > 0)   ? x[i - 512]   : zero;
        float4 wp = (w < 127) ? x[i + 4]     : zero;
        float4 wm = (w > 0)   ? x[i - 4]     : zero;
        float4 tp = (t < 15)  ? x[i + 65536] : zero;
        float4 tm = (t > 0)   ? x[i - 65536] : zero;

        __stcs(&out[i],                sub4(hp, hm));  // dy
        __stcs(&out[i + N4_TOTAL],     sub4(wp, wm));  // dx
        __stcs(&out[i + 2 * N4_TOTAL], sub4(tp, tm));  // dz
    }
}

extern "C" void kernel_launch(void* const* d_in, const int* in_sizes, int n_in,
                              void* d_out, int out_size)
{
    const float4* x = (const float4*)d_in[0];
    float4* out = (float4*)d_out;

    fd_kernel<<<NBLOCKS, 256>>>(x, out);
}

// round 11
// speedup vs baseline: 1.2811x; 1.2811x over previous
#include <cuda_runtime.h>

// FiniteDifference: x [B=4, T=16, H=128, W=128, C=16] fp32
// out = concat(dy (d/dH), dx (d/dW), dz (d/dT)); central diff, zero pad.
//
// FINAL (validated over R1-R10): fused 1-float4/thread, flat grid.
// Model: DRAM traffic == ~201 MB compulsory write stream (input L2-resident,
// reads ~free); write-drain throughput is ~5.3 TB/s and independent of store
// path/pattern (STG == __stcs == v8 == TMA bulk == axis-split == block shape
// == persistence, all measured). This kernel runs at ~96% of that floor.
// Rejected alternatives: 2x MLP/thread (occ cliff, +31%), axis-split CTAs
// (L2 reuse broken, +52%), v8 ops (+3%), TMA bulk stores (+4%), block=512
// (+1.5%), persistent grid-stride (+33%).

#define N4_TOTAL (4 * 16 * 128 * 128 * 4)  // 4,194,304 float4 elems per output

__device__ __forceinline__ float4 sub4(float4 a, float4 b) {
    return make_float4(a.x - b.x, a.y - b.y, a.z - b.z, a.w - b.w);
}

__global__ void __launch_bounds__(256)
fd_kernel(const float4* __restrict__ x, float4* __restrict__ out)
{
    int i = blockIdx.x * blockDim.x + threadIdx.x;

    int w = (i >> 2)  & 127;
    int h = (i >> 9)  & 127;
    int t = (i >> 16) & 15;

    const float4 zero = make_float4(0.f, 0.f, 0.f, 0.f);

    float4 hp = (h < 127) ? x[i + 512]   : zero;
    float4 hm = (h > 0)   ? x[i - 512]   : zero;
    float4 wp = (w < 127) ? x[i + 4]     : zero;
    float4 wm = (w > 0)   ? x[i - 4]     : zero;
    float4 tp = (t < 15)  ? x[i + 65536] : zero;
    float4 tm = (t > 0)   ? x[i - 65536] : zero;

    __stcs(&out[i],                sub4(hp, hm));  // dy
    __stcs(&out[i + N4_TOTAL],     sub4(wp, wm));  // dx
    __stcs(&out[i + 2 * N4_TOTAL], sub4(tp, tm));  // dz
}

extern "C" void kernel_launch(void* const* d_in, const int* in_sizes, int n_in,
                              void* d_out, int out_size)
{
    const float4* x = (const float4*)d_in[0];
    float4* out = (float4*)d_out;

    fd_kernel<<<N4_TOTAL / 256, 256>>>(x, out);
}

// round 12
// speedup vs baseline: 1.3292x; 1.0376x over previous
#include <cuda_runtime.h>

// FiniteDifference: x [B=4, T=16, H=128, W=128, C=16] fp32
// out = concat(dy (d/dH), dx (d/dW), dz (d/dT)); central diff, zero pad.
//
// FINAL — roofline kernel, validated over 11 rounds / 9 structural variants.
//
// Model: DRAM traffic == ~201 MB compulsory write stream; the 64 MiB input
// stays L2-resident across graph replays so reads are ~free. Write-drain
// throughput plateaus at ~5.3 TB/s and is independent of store width
// (.128/.256), store path (STG/__stcs/TMA bulk), stream mix (fused vs
// axis-split), block shape (128-512), wave structure (flat vs persistent),
// and occupancy (40-93%). This kernel runs at ~96% of the resulting
// 201 MB / 5.3 TB/s ~= 38 us floor.
//
// Rejected (measured): 2x MLP/thread +31% (occupancy cliff), axis-split
// CTAs +52% (breaks L2 reuse, +70% DRAM traffic), v8 ops +3%, TMA bulk
// stores +4%, block=512 +1.5%, persistent grid-stride +33% (reg pressure +
// L2 reuse spread), store reordering neutral.

#define N4_TOTAL (4 * 16 * 128 * 128 * 4)  // 4,194,304 float4 elems per output

__device__ __forceinline__ float4 sub4(float4 a, float4 b) {
    return make_float4(a.x - b.x, a.y - b.y, a.z - b.z, a.w - b.w);
}

__global__ void __launch_bounds__(256)
fd_kernel(const float4* __restrict__ x, float4* __restrict__ out)
{
    int i = blockIdx.x * blockDim.x + threadIdx.x;

    int w = (i >> 2)  & 127;
    int h = (i >> 9)  & 127;
    int t = (i >> 16) & 15;

    const float4 zero = make_float4(0.f, 0.f, 0.f, 0.f);

    float4 hp = (h < 127) ? x[i + 512]   : zero;
    float4 hm = (h > 0)   ? x[i - 512]   : zero;
    float4 wp = (w < 127) ? x[i + 4]     : zero;
    float4 wm = (w > 0)   ? x[i - 4]     : zero;
    float4 tp = (t < 15)  ? x[i + 65536] : zero;
    float4 tm = (t > 0)   ? x[i - 65536] : zero;

    __stcs(&out[i],                sub4(hp, hm));  // dy
    __stcs(&out[i + N4_TOTAL],     sub4(wp, wm));  // dx
    __stcs(&out[i + 2 * N4_TOTAL], sub4(tp, tm));  // dz
}

extern "C" void kernel_launch(void* const* d_in, const int* in_sizes, int n_in,
                              void* d_out, int out_size)
{
    const float4* x = (const float4*)d_in[0];
    float4* out = (float4*)d_out;

    fd_kernel<<<N4_TOTAL / 256, 256>>>(x, out);
}